// round 10
// baseline (speedup 1.0000x reference)
#include <cuda_runtime.h>
#include <cuda_bf16.h>

#define NMAX   50000
#define D      96
#define D4     24
#define TM     128
#define STRA   104    // A tile row stride (bf16 elems) -> conflict-free frags
#define STRW   104    // Wt tile row stride

typedef unsigned int  u32;
typedef unsigned short ushort_t;

// ---------------- scratch (device globals; no allocation allowed) ----------
// INVARIANT: g_pool, g_sum, g_sumsq are all-zero at kernel_launch entry.
// (zero-initialized at module load; mlp_kernel re-zeroes pool tiles after
//  reading them; scatter_kernel block 0 re-zeroes the BN accumulators before
//  mlp_kernel runs.)
__device__ float4 g_pool[NMAX * D4];            // pooled neighbor sums (19.2 MB)
__device__ float  g_sum[D];
__device__ float  g_sumsq[D];

// ---------------- K1: edge scatter: pool[dst] += feature[src] ---------------
// 8 threads per edge, 3 float4 chunks per thread (chunks j, j+8, j+16)
__global__ void scatter_kernel(const float4* __restrict__ feat,
                               const int* __restrict__ src,
                               const int* __restrict__ dst, int total) {
    int i = blockIdx.x * blockDim.x + threadIdx.x;
    if (blockIdx.x == 0 && threadIdx.x < 2 * D) {
        // re-zero BN accumulators for this launch (ordered before mlp_kernel)
        if (threadIdx.x < D) g_sum[threadIdx.x] = 0.f;
        else                 g_sumsq[threadIdx.x - D] = 0.f;
    }
    if (i >= total) return;
    int e = i >> 3;
    int j = i & 7;
    int s = __ldg(src + e);
    int d = __ldg(dst + e);
    const float4* fp = feat + (long)s * D4 + j;
    float4* pp = g_pool + (long)d * D4 + j;
    float4 v0 = __ldg(fp);
    float4 v1 = __ldg(fp + 8);
    float4 v2 = __ldg(fp + 16);
    asm volatile("red.global.add.v4.f32 [%0], {%1,%2,%3,%4};"
                 :: "l"(pp), "f"(v0.x), "f"(v0.y), "f"(v0.z), "f"(v0.w) : "memory");
    asm volatile("red.global.add.v4.f32 [%0], {%1,%2,%3,%4};"
                 :: "l"(pp + 8), "f"(v1.x), "f"(v1.y), "f"(v1.z), "f"(v1.w) : "memory");
    asm volatile("red.global.add.v4.f32 [%0], {%1,%2,%3,%4};"
                 :: "l"(pp + 16), "f"(v2.x), "f"(v2.y), "f"(v2.z), "f"(v2.w) : "memory");
}

// ---------------- K2: tensor-core MLP + BN stats -----------------------------
#define MMA_BF16(c, a0, a1, a2, a3, b0, b1) \
    asm volatile("mma.sync.aligned.m16n8k16.row.col.f32.bf16.bf16.f32 " \
                 "{%0,%1,%2,%3}, {%4,%5,%6,%7}, {%8,%9}, {%0,%1,%2,%3};" \
                 : "+f"((c)[0]), "+f"((c)[1]), "+f"((c)[2]), "+f"((c)[3]) \
                 : "r"(a0), "r"(a1), "r"(a2), "r"(a3), "r"(b0), "r"(b1))

__device__ __forceinline__ void split_store(ushort_t* hi, ushort_t* lo,
                                            float v0, float v1) {
    __nv_bfloat162 h = __float22bfloat162_rn(make_float2(v0, v1));
    float2 rf = make_float2(v0 - __bfloat162float(h.x),
                            v1 - __bfloat162float(h.y));
    __nv_bfloat162 l = __float22bfloat162_rn(rf);
    *(u32*)hi = *(u32*)&h;
    *(u32*)lo = *(u32*)&l;
}

__device__ __forceinline__ void do_gemm(const ushort_t* __restrict__ Ahi,
                                        const ushort_t* __restrict__ Alo,
                                        const ushort_t* __restrict__ Whi,
                                        const ushort_t* __restrict__ Wlo,
                                        float c[12][4], int ar0, int tq, int g) {
    for (int kt = 0; kt < 6; kt++) {
        int kc = kt * 16 + tq * 2;
        const ushort_t* pah = Ahi + ar0 * STRA + kc;
        const ushort_t* pal = Alo + ar0 * STRA + kc;
        u32 ah0 = *(const u32*)(pah);
        u32 ah1 = *(const u32*)(pah + 8 * STRA);
        u32 ah2 = *(const u32*)(pah + 8);
        u32 ah3 = *(const u32*)(pah + 8 * STRA + 8);
        u32 al0 = *(const u32*)(pal);
        u32 al1 = *(const u32*)(pal + 8 * STRA);
        u32 al2 = *(const u32*)(pal + 8);
        u32 al3 = *(const u32*)(pal + 8 * STRA + 8);
        #pragma unroll
        for (int nt = 0; nt < 12; nt++) {
            const ushort_t* pbh = Whi + (nt * 8 + g) * STRW + kc;
            const ushort_t* pbl = Wlo + (nt * 8 + g) * STRW + kc;
            u32 bh0 = *(const u32*)(pbh);
            u32 bh1 = *(const u32*)(pbh + 8);
            u32 bl0 = *(const u32*)(pbl);
            u32 bl1 = *(const u32*)(pbl + 8);
            MMA_BF16(c[nt], ah0, ah1, ah2, ah3, bh0, bh1);
            MMA_BF16(c[nt], ah0, ah1, ah2, ah3, bl0, bl1);
            MMA_BF16(c[nt], al0, al1, al2, al3, bh0, bh1);
        }
    }
}

#define A_ELEMS (TM * STRA)   // 13312
#define W_ELEMS (D * STRW)    // 9984

__global__ __launch_bounds__(256, 2)
void mlp_kernel(const float4* __restrict__ feat,
                const float* __restrict__ eps,
                const float* __restrict__ W1, const float* __restrict__ b1,
                const float* __restrict__ W2, const float* __restrict__ b2,
                float* __restrict__ out, int n) {
    extern __shared__ ushort_t smem[];
    ushort_t* Ahi = smem;
    ushort_t* Alo = Ahi + A_ELEMS;
    ushort_t* Whi = Alo + A_ELEMS;
    ushort_t* Wlo = Whi + W_ELEMS;
    float* s_sum = (float*)(Wlo + W_ELEMS);
    float* s_sq  = s_sum + D;

    const int tid  = threadIdx.x;
    const int lane = tid & 31;
    const int warp = tid >> 5;
    const int tq   = lane & 3;
    const int g    = lane >> 2;
    const int rb   = blockIdx.x * TM;
    const int ar0  = warp * 16 + g;

    if (tid < D) { s_sum[tid] = 0.f; s_sq[tid] = 0.f; }

    // ---- stage A = pool + (1+eps)*feat (bf16 split); re-zero pool tile ----
    const float se = 1.0f + __ldg(eps);
    const float4 z4 = make_float4(0.f, 0.f, 0.f, 0.f);
    for (int i = tid; i < TM * D4; i += 256) {
        int r  = i / D4;
        int c4 = i - r * D4;
        float4 v = z4;
        if (rb + r < n) {
            long idx = (long)(rb + r) * D4 + c4;
            float4 p = g_pool[idx];
            g_pool[idx] = z4;            // restore pool==0 invariant for next replay
            float4 f = __ldg(feat + idx);
            v.x = fmaf(se, f.x, p.x);
            v.y = fmaf(se, f.y, p.y);
            v.z = fmaf(se, f.z, p.z);
            v.w = fmaf(se, f.w, p.w);
        }
        int off = r * STRA + c4 * 4;
        split_store(Ahi + off,     Alo + off,     v.x, v.y);
        split_store(Ahi + off + 2, Alo + off + 2, v.z, v.w);
    }
    // ---- stage W1 transposed (Wt[n][k]), bf16 split ----
    for (int i = tid; i < D * D; i += 256) {
        int k  = i / D;
        int nn = i - k * D;
        float wv = __ldg(W1 + i);
        __nv_bfloat16 h = __float2bfloat16(wv);
        Whi[nn * STRW + k] = __bfloat16_as_ushort(h);
        Wlo[nn * STRW + k] =
            __bfloat16_as_ushort(__float2bfloat16(wv - __bfloat162float(h)));
    }
    __syncthreads();

    float c[12][4];
    #pragma unroll
    for (int nt = 0; nt < 12; nt++)
        #pragma unroll
        for (int q = 0; q < 4; q++) c[nt][q] = 0.f;

    // ---- GEMM1 ----
    do_gemm(Ahi, Alo, Whi, Wlo, c, ar0, tq, g);
    __syncthreads();

    // ---- h1 = relu(c + b1) -> split back into A tiles ----
    #pragma unroll
    for (int nt = 0; nt < 12; nt++) {
        int n0 = nt * 8 + tq * 2;
        float bb0 = __ldg(b1 + n0);
        float bb1 = __ldg(b1 + n0 + 1);
        float v00 = fmaxf(c[nt][0] + bb0, 0.f);
        float v01 = fmaxf(c[nt][1] + bb1, 0.f);
        float v10 = fmaxf(c[nt][2] + bb0, 0.f);
        float v11 = fmaxf(c[nt][3] + bb1, 0.f);
        int r0 = (warp * 16 + g) * STRA + n0;
        int r1 = r0 + 8 * STRA;
        split_store(Ahi + r0, Alo + r0, v00, v01);
        split_store(Ahi + r1, Alo + r1, v10, v11);
    }
    // ---- stage W2 transposed ----
    for (int i = tid; i < D * D; i += 256) {
        int k  = i / D;
        int nn = i - k * D;
        float wv = __ldg(W2 + i);
        __nv_bfloat16 h = __float2bfloat16(wv);
        Whi[nn * STRW + k] = __bfloat16_as_ushort(h);
        Wlo[nn * STRW + k] =
            __bfloat16_as_ushort(__float2bfloat16(wv - __bfloat162float(h)));
    }
    __syncthreads();

    #pragma unroll
    for (int nt = 0; nt < 12; nt++)
        #pragma unroll
        for (int q = 0; q < 4; q++) c[nt][q] = 0.f;

    // ---- GEMM2 ----
    do_gemm(Ahi, Alo, Whi, Wlo, c, ar0, tq, g);

    // ---- epilogue: +b2, store h2, BN sums ----
    #pragma unroll
    for (int nt = 0; nt < 12; nt++) {
        int n0 = nt * 8 + tq * 2;
        float bb0 = __ldg(b2 + n0);
        float bb1 = __ldg(b2 + n0 + 1);
        int row0 = rb + warp * 16 + g;
        int row1 = row0 + 8;
        float v00 = c[nt][0] + bb0;
        float v01 = c[nt][1] + bb1;
        float v10 = c[nt][2] + bb0;
        float v11 = c[nt][3] + bb1;
        float s0 = 0.f, s1 = 0.f, q0 = 0.f, q1 = 0.f;
        if (row0 < n) {
            *(float2*)(out + (long)row0 * D + n0) = make_float2(v00, v01);
            s0 += v00; s1 += v01; q0 += v00 * v00; q1 += v01 * v01;
        }
        if (row1 < n) {
            *(float2*)(out + (long)row1 * D + n0) = make_float2(v10, v11);
            s0 += v10; s1 += v11; q0 += v10 * v10; q1 += v11 * v11;
        }
        #pragma unroll
        for (int m = 4; m < 32; m <<= 1) {
            s0 += __shfl_xor_sync(0xffffffffu, s0, m);
            s1 += __shfl_xor_sync(0xffffffffu, s1, m);
            q0 += __shfl_xor_sync(0xffffffffu, q0, m);
            q1 += __shfl_xor_sync(0xffffffffu, q1, m);
        }
        if (g == 0) {
            atomicAdd(&s_sum[n0],     s0);
            atomicAdd(&s_sum[n0 + 1], s1);
            atomicAdd(&s_sq[n0],      q0);
            atomicAdd(&s_sq[n0 + 1],  q1);
        }
    }
    __syncthreads();
    if (tid < D) {
        atomicAdd(&g_sum[tid],   s_sum[tid]);
        atomicAdd(&g_sumsq[tid], s_sq[tid]);
    }
}

// ---------------- K3: apply BN + ReLU, 1 float4 per thread -------------------
__global__ void apply_kernel(const float* __restrict__ gamma,
                             const float* __restrict__ beta,
                             float invN, float4* __restrict__ out4, int n4) {
    __shared__ __align__(16) float sc[D];
    __shared__ __align__(16) float sh[D];
    int tid = threadIdx.x;
    if (tid < D) {
        float mean = g_sum[tid] * invN;
        float var  = g_sumsq[tid] * invN - mean * mean;
        float rstd = rsqrtf(var + 1e-5f);
        float s    = rstd * gamma[tid];
        sc[tid] = s;
        sh[tid] = beta[tid] - mean * s;
    }
    __syncthreads();

    int i = blockIdx.x * blockDim.x + tid;
    if (i >= n4) return;
    int c4 = i % D4;
    float4 h  = out4[i];
    float4 s4 = ((const float4*)sc)[c4];
    float4 h4 = ((const float4*)sh)[c4];
    h.x = fmaxf(fmaf(h.x, s4.x, h4.x), 0.f);
    h.y = fmaxf(fmaf(h.y, s4.y, h4.y), 0.f);
    h.z = fmaxf(fmaf(h.z, s4.z, h4.z), 0.f);
    h.w = fmaxf(fmaf(h.w, s4.w, h4.w), 0.f);
    out4[i] = h;
}

// ---------------------------------------------------------------------------
extern "C" void kernel_launch(void* const* d_in, const int* in_sizes, int n_in,
                              void* d_out, int out_size) {
    const float* feature = (const float*)d_in[0];
    const int*   src     = (const int*)d_in[1];
    const int*   dst     = (const int*)d_in[2];
    const float* W1      = (const float*)d_in[3];
    const float* b1      = (const float*)d_in[4];
    const float* W2      = (const float*)d_in[5];
    const float* b2      = (const float*)d_in[6];
    const float* gamma   = (const float*)d_in[7];
    const float* beta    = (const float*)d_in[8];
    const float* eps     = (const float*)d_in[9];
    float* out = (float*)d_out;

    const int n  = in_sizes[0] / D;     // 50000
    const int E  = in_sizes[1];         // 800000
    const int n4 = n * D4;

    int total = E * 8;
    scatter_kernel<<<(total + 255) / 256, 256>>>((const float4*)feature,
                                                 src, dst, total);

    const int SMEM = (2 * A_ELEMS + 2 * W_ELEMS) * 2 + 2 * D * 4; // 93952 B
    cudaFuncSetAttribute(mlp_kernel,
                         cudaFuncAttributeMaxDynamicSharedMemorySize, SMEM);
    mlp_kernel<<<(n + TM - 1) / TM, 256, SMEM>>>((const float4*)feature, eps,
                                                 W1, b1, W2, b2, out, n);

    apply_kernel<<<(n4 + 255) / 256, 256>>>(gamma, beta, 1.0f / (float)n,
                                            (float4*)out, n4);
}

// round 12
// speedup vs baseline: 1.5010x; 1.5010x over previous
#include <cuda_runtime.h>
#include <cuda_bf16.h>

#define NMAX   50000
#define D      96
#define D4     24
#define TM     128
#define STRW   104    // Wt tile row stride (bf16 elems)

typedef unsigned int  u32;
typedef unsigned short ushort_t;

// ---------------- scratch (device globals; no allocation allowed) ----------
__device__ float4 g_pool[NMAX * D4];            // pooled neighbor sums (19.2 MB)
__device__ float  g_sum[D];
__device__ float  g_sumsq[D];

// ---------------- K1: zero pool + BN accumulators ---------------------------
__global__ void zero_kernel(int n4) {
    int i = blockIdx.x * blockDim.x + threadIdx.x;
    if (i < D) { g_sum[i] = 0.f; g_sumsq[i] = 0.f; }
    if (i >= n4) return;
    g_pool[i] = make_float4(0.f, 0.f, 0.f, 0.f);
}

// ---------------- K2: edge scatter: pool[dst] += feature[src] ---------------
// 8 threads per edge, 3 float4 chunks per thread (chunks j, j+8, j+16)
__global__ void scatter_kernel(const float4* __restrict__ feat,
                               const int* __restrict__ src,
                               const int* __restrict__ dst, int total) {
    int i = blockIdx.x * blockDim.x + threadIdx.x;
    if (i >= total) return;
    int e = i >> 3;
    int j = i & 7;
    int s = __ldg(src + e);
    int d = __ldg(dst + e);
    const float4* fp = feat + (long)s * D4 + j;
    float4* pp = g_pool + (long)d * D4 + j;
    float4 v0 = __ldg(fp);
    float4 v1 = __ldg(fp + 8);
    float4 v2 = __ldg(fp + 16);
    asm volatile("red.global.add.v4.f32 [%0], {%1,%2,%3,%4};"
                 :: "l"(pp), "f"(v0.x), "f"(v0.y), "f"(v0.z), "f"(v0.w) : "memory");
    asm volatile("red.global.add.v4.f32 [%0], {%1,%2,%3,%4};"
                 :: "l"(pp + 8), "f"(v1.x), "f"(v1.y), "f"(v1.z), "f"(v1.w) : "memory");
    asm volatile("red.global.add.v4.f32 [%0], {%1,%2,%3,%4};"
                 :: "l"(pp + 16), "f"(v2.x), "f"(v2.y), "f"(v2.z), "f"(v2.w) : "memory");
}

// ---------------- K3: tensor-core MLP + BN stats -----------------------------
// A fragments built directly from global (pool + (1+eps)*feat, bf16-split);
// h1 stays entirely in registers (C-fragment of GEMM1 == A-fragment of GEMM2).
#define MMA_BF16(c, a0, a1, a2, a3, b0, b1) \
    asm volatile("mma.sync.aligned.m16n8k16.row.col.f32.bf16.bf16.f32 " \
                 "{%0,%1,%2,%3}, {%4,%5,%6,%7}, {%8,%9}, {%0,%1,%2,%3};" \
                 : "+f"((c)[0]), "+f"((c)[1]), "+f"((c)[2]), "+f"((c)[3]) \
                 : "r"(a0), "r"(a1), "r"(a2), "r"(a3), "r"(b0), "r"(b1))

__device__ __forceinline__ void split_pack(float v0, float v1, u32& hi, u32& lo) {
    __nv_bfloat162 h = __float22bfloat162_rn(make_float2(v0, v1));
    float2 rf = make_float2(v0 - __bfloat162float(h.x),
                            v1 - __bfloat162float(h.y));
    __nv_bfloat162 l = __float22bfloat162_rn(rf);
    hi = *(u32*)&h;
    lo = *(u32*)&l;
}

#define W_ELEMS (D * STRW)    // 9984

__global__ __launch_bounds__(256, 2)
void mlp_kernel(const float* __restrict__ featf,
                const float* __restrict__ eps,
                const float* __restrict__ W1, const float* __restrict__ b1,
                const float* __restrict__ W2, const float* __restrict__ b2,
                float* __restrict__ out, int n) {
    extern __shared__ ushort_t smem[];
    ushort_t* W1hi = smem;
    ushort_t* W1lo = W1hi + W_ELEMS;
    ushort_t* W2hi = W1lo + W_ELEMS;
    ushort_t* W2lo = W2hi + W_ELEMS;
    float* s_sum = (float*)(W2lo + W_ELEMS);
    float* s_sq  = s_sum + D;

    const int tid  = threadIdx.x;
    const int lane = tid & 31;
    const int warp = tid >> 5;           // warp owns rows [warp*16, +16)
    const int tq   = lane & 3;
    const int g    = lane >> 2;
    const int rb   = blockIdx.x * TM;

    if (tid < D) { s_sum[tid] = 0.f; s_sq[tid] = 0.f; }

    // ---- stage W1 and W2 transposed (Wt[n][k]), bf16 split ----
    for (int i = tid; i < D * D; i += 256) {
        int k  = i / D;
        int nn = i - k * D;
        int off = nn * STRW + k;
        float wv1 = __ldg(W1 + i);
        float wv2 = __ldg(W2 + i);
        __nv_bfloat16 h1v = __float2bfloat16(wv1);
        __nv_bfloat16 h2v = __float2bfloat16(wv2);
        W1hi[off] = __bfloat16_as_ushort(h1v);
        W1lo[off] = __bfloat16_as_ushort(
                        __float2bfloat16(wv1 - __bfloat162float(h1v)));
        W2hi[off] = __bfloat16_as_ushort(h2v);
        W2lo[off] = __bfloat16_as_ushort(
                        __float2bfloat16(wv2 - __bfloat162float(h2v)));
    }
    __syncthreads();

    const float se   = 1.0f + __ldg(eps);
    const int   row0 = rb + warp * 16 + g;      // global rows this lane covers
    const int   row1 = row0 + 8;
    const bool  ok0  = row0 < n;
    const bool  ok1  = row1 < n;
    const float2* pool2 = (const float2*)g_pool;
    const float2* feat2 = (const float2*)featf;
    const float2  z2 = make_float2(0.f, 0.f);

    float c[12][4];
    #pragma unroll
    for (int nt = 0; nt < 12; nt++)
        #pragma unroll
        for (int q = 0; q < 4; q++) c[nt][q] = 0.f;

    // ---- GEMM1: A frags direct from global ----
    #pragma unroll
    for (int kt = 0; kt < 6; kt++) {
        int kc = kt * 16 + tq * 2;          // even column
        long i00 = (long)row0 * 48 + (kc >> 1);
        long i10 = (long)row1 * 48 + (kc >> 1);
        float2 p00 = ok0 ? pool2[i00]     : z2;
        float2 p10 = ok1 ? pool2[i10]     : z2;
        float2 p01 = ok0 ? pool2[i00 + 4] : z2;   // +8 cols = +4 float2
        float2 p11 = ok1 ? pool2[i10 + 4] : z2;
        float2 f00 = ok0 ? __ldg(feat2 + i00)     : z2;
        float2 f10 = ok1 ? __ldg(feat2 + i10)     : z2;
        float2 f01 = ok0 ? __ldg(feat2 + i00 + 4) : z2;
        float2 f11 = ok1 ? __ldg(feat2 + i10 + 4) : z2;
        u32 ah[4], al[4];
        split_pack(fmaf(se, f00.x, p00.x), fmaf(se, f00.y, p00.y), ah[0], al[0]);
        split_pack(fmaf(se, f10.x, p10.x), fmaf(se, f10.y, p10.y), ah[1], al[1]);
        split_pack(fmaf(se, f01.x, p01.x), fmaf(se, f01.y, p01.y), ah[2], al[2]);
        split_pack(fmaf(se, f11.x, p11.x), fmaf(se, f11.y, p11.y), ah[3], al[3]);
        #pragma unroll
        for (int nt = 0; nt < 12; nt++) {
            const ushort_t* pbh = W1hi + (nt * 8 + g) * STRW + kc;
            const ushort_t* pbl = W1lo + (nt * 8 + g) * STRW + kc;
            u32 bh0 = *(const u32*)(pbh);
            u32 bh1 = *(const u32*)(pbh + 8);
            u32 bl0 = *(const u32*)(pbl);
            u32 bl1 = *(const u32*)(pbl + 8);
            MMA_BF16(c[nt], ah[0], ah[1], ah[2], ah[3], bh0, bh1);
            MMA_BF16(c[nt], ah[0], ah[1], ah[2], ah[3], bl0, bl1);
            MMA_BF16(c[nt], al[0], al[1], al[2], al[3], bh0, bh1);
        }
    }

    // ---- h1 = relu(c + b1), packed in registers (== GEMM2 A-fragments) ----
    u32 hh[12][2], hl[12][2];
    #pragma unroll
    for (int nt = 0; nt < 12; nt++) {
        int n0 = nt * 8 + tq * 2;
        float bb0 = __ldg(b1 + n0);
        float bb1 = __ldg(b1 + n0 + 1);
        float v00 = fmaxf(c[nt][0] + bb0, 0.f);
        float v01 = fmaxf(c[nt][1] + bb1, 0.f);
        float v10 = fmaxf(c[nt][2] + bb0, 0.f);
        float v11 = fmaxf(c[nt][3] + bb1, 0.f);
        split_pack(v00, v01, hh[nt][0], hl[nt][0]);
        split_pack(v10, v11, hh[nt][1], hl[nt][1]);
    }

    #pragma unroll
    for (int nt = 0; nt < 12; nt++)
        #pragma unroll
        for (int q = 0; q < 4; q++) c[nt][q] = 0.f;

    // ---- GEMM2: A frags straight from h1 registers ----
    #pragma unroll
    for (int kt = 0; kt < 6; kt++) {
        int kc = kt * 16 + tq * 2;
        u32 ah0 = hh[2 * kt][0],     al0 = hl[2 * kt][0];
        u32 ah1 = hh[2 * kt][1],     al1 = hl[2 * kt][1];
        u32 ah2 = hh[2 * kt + 1][0], al2 = hl[2 * kt + 1][0];
        u32 ah3 = hh[2 * kt + 1][1], al3 = hl[2 * kt + 1][1];
        #pragma unroll
        for (int nt = 0; nt < 12; nt++) {
            const ushort_t* pbh = W2hi + (nt * 8 + g) * STRW + kc;
            const ushort_t* pbl = W2lo + (nt * 8 + g) * STRW + kc;
            u32 bh0 = *(const u32*)(pbh);
            u32 bh1 = *(const u32*)(pbh + 8);
            u32 bl0 = *(const u32*)(pbl);
            u32 bl1 = *(const u32*)(pbl + 8);
            MMA_BF16(c[nt], ah0, ah1, ah2, ah3, bh0, bh1);
            MMA_BF16(c[nt], ah0, ah1, ah2, ah3, bl0, bl1);
            MMA_BF16(c[nt], al0, al1, al2, al3, bh0, bh1);
        }
    }

    // ---- epilogue: +b2, store h2, BN sums ----
    #pragma unroll
    for (int nt = 0; nt < 12; nt++) {
        int n0 = nt * 8 + tq * 2;
        float bb0 = __ldg(b2 + n0);
        float bb1 = __ldg(b2 + n0 + 1);
        float v00 = c[nt][0] + bb0;
        float v01 = c[nt][1] + bb1;
        float v10 = c[nt][2] + bb0;
        float v11 = c[nt][3] + bb1;
        float s0 = 0.f, s1 = 0.f, q0 = 0.f, q1 = 0.f;
        if (ok0) {
            *(float2*)(out + (long)row0 * D + n0) = make_float2(v00, v01);
            s0 += v00; s1 += v01; q0 += v00 * v00; q1 += v01 * v01;
        }
        if (ok1) {
            *(float2*)(out + (long)row1 * D + n0) = make_float2(v10, v11);
            s0 += v10; s1 += v11; q0 += v10 * v10; q1 += v11 * v11;
        }
        #pragma unroll
        for (int m = 4; m < 32; m <<= 1) {
            s0 += __shfl_xor_sync(0xffffffffu, s0, m);
            s1 += __shfl_xor_sync(0xffffffffu, s1, m);
            q0 += __shfl_xor_sync(0xffffffffu, q0, m);
            q1 += __shfl_xor_sync(0xffffffffu, q1, m);
        }
        if (g == 0) {
            atomicAdd(&s_sum[n0],     s0);
            atomicAdd(&s_sum[n0 + 1], s1);
            atomicAdd(&s_sq[n0],      q0);
            atomicAdd(&s_sq[n0 + 1],  q1);
        }
    }
    __syncthreads();
    if (tid < D) {
        atomicAdd(&g_sum[tid],   s_sum[tid]);
        atomicAdd(&g_sumsq[tid], s_sq[tid]);
    }
}

// ---------------- K4: apply BN + ReLU, 1 float4 per thread -------------------
__global__ void apply_kernel(const float* __restrict__ gamma,
                             const float* __restrict__ beta,
                             float invN, float4* __restrict__ out4, int n4) {
    __shared__ __align__(16) float sc[D];
    __shared__ __align__(16) float sh[D];
    int tid = threadIdx.x;
    if (tid < D) {
        float mean = g_sum[tid] * invN;
        float var  = g_sumsq[tid] * invN - mean * mean;
        float rstd = rsqrtf(var + 1e-5f);
        float s    = rstd * gamma[tid];
        sc[tid] = s;
        sh[tid] = beta[tid] - mean * s;
    }
    __syncthreads();

    int i = blockIdx.x * blockDim.x + tid;
    if (i >= n4) return;
    int c4 = i % D4;
    float4 h  = out4[i];
    float4 s4 = ((const float4*)sc)[c4];
    float4 h4 = ((const float4*)sh)[c4];
    h.x = fmaxf(fmaf(h.x, s4.x, h4.x), 0.f);
    h.y = fmaxf(fmaf(h.y, s4.y, h4.y), 0.f);
    h.z = fmaxf(fmaf(h.z, s4.z, h4.z), 0.f);
    h.w = fmaxf(fmaf(h.w, s4.w, h4.w), 0.f);
    out4[i] = h;
}

// ---------------------------------------------------------------------------
extern "C" void kernel_launch(void* const* d_in, const int* in_sizes, int n_in,
                              void* d_out, int out_size) {
    const float* feature = (const float*)d_in[0];
    const int*   src     = (const int*)d_in[1];
    const int*   dst     = (const int*)d_in[2];
    const float* W1      = (const float*)d_in[3];
    const float* b1      = (const float*)d_in[4];
    const float* W2      = (const float*)d_in[5];
    const float* b2      = (const float*)d_in[6];
    const float* gamma   = (const float*)d_in[7];
    const float* beta    = (const float*)d_in[8];
    const float* eps     = (const float*)d_in[9];
    float* out = (float*)d_out;

    const int n  = in_sizes[0] / D;     // 50000
    const int E  = in_sizes[1];         // 800000
    const int n4 = n * D4;

    zero_kernel<<<(n4 + 255) / 256, 256>>>(n4);

    int total = E * 8;
    scatter_kernel<<<(total + 255) / 256, 256>>>((const float4*)feature,
                                                 src, dst, total);

    const int SMEM = 4 * W_ELEMS * 2 + 2 * D * 4;   // 80640 B
    cudaFuncSetAttribute(mlp_kernel,
                         cudaFuncAttributeMaxDynamicSharedMemorySize, SMEM);
    mlp_kernel<<<(n + TM - 1) / TM, 256, SMEM>>>(feature, eps,
                                                 W1, b1, W2, b2, out, n);

    apply_kernel<<<(n4 + 255) / 256, 256>>>(gamma, beta, 1.0f / (float)n,
                                            (float4*)out, n4);
}